// round 12
// baseline (speedup 1.0000x reference)
#include <cuda_runtime.h>
#include <cstdint>
#include <cstddef>

// Monarch embedding, analytically folded:
//   out[tok][kr*32+o] = (kr&1 == s) ? L[v*16 + kr/2] * R[(kr*32 + c)*32 + o] : 0
//   v = x[tok], k = v/786, s = k>>5, c = k&31.
//
// R12: single-kernel binning -> R fully register-resident.
// Grid 128 = 64 bins x 2 halves, 512 threads. Per CTA:
//   phase 1: scan 8192 tokens of x (coalesced), push matches (k==bin) into
//            an smem list via smem atomics (~128 entries, order-free).
//   phase 2: c,s are CTA constants -> each thread's 8-float R slice (with
//            parity zeros pre-folded) lives in registers. Token loop does
//            only: uniform LDS (list) + L scalar LDG (depth-2 prefetch) +
//            8 FMUL + 1 STG.256. Zero R traffic in the hot loop.
// Output per token = its own row -> atomic list order doesn't affect result.
//
// Thread map (phase 2): group g = tid>>7 handles every 4th list entry;
//   slot = tid&127, kr = slot>>2, osub = (slot&3)*8, i = kr>>1, p = kr&1.

#define NBIN   64
#define HALF   8192              // tokens per sub-CTA scan range
#define LCAP   1024              // smem list capacity (mean 128, huge margin)

__global__ void __launch_bounds__(512, 1) monarch_bin_kernel(
    const int* __restrict__ x,
    const float* __restrict__ L,
    const float* __restrict__ R,
    float* __restrict__ out)
{
    __shared__ int  s_cnt;
    __shared__ int2 s_list[LCAP];

    const int bin = blockIdx.x >> 1;        // 0..63
    const int sub = blockIdx.x & 1;         // which half of x
    const int s   = bin >> 5;
    const int c   = bin & 31;

    const int tid  = threadIdx.x;
    const int g    = tid >> 7;              // token-group 0..3
    const int slot = tid & 127;
    const int kr   = slot >> 2;             // 0..31
    const int osub = (slot & 3) << 3;       // 0,8,16,24
    const int i    = kr >> 1;               // L column
    const int p    = kr & 1;                // row parity

    // Register-resident R slice, parity pre-folded.
    float r0=0.f,r1=0.f,r2=0.f,r3=0.f,r4=0.f,r5=0.f,r6=0.f,r7=0.f;
    if (p == s) {
        const float4 a = *reinterpret_cast<const float4*>(
            &R[((size_t)((kr << 5) + c) << 5) + osub]);
        const float4 b = *reinterpret_cast<const float4*>(
            &R[((size_t)((kr << 5) + c) << 5) + osub + 4]);
        r0=a.x; r1=a.y; r2=a.z; r3=a.w; r4=b.x; r5=b.y; r6=b.z; r7=b.w;
    }

    if (tid == 0) s_cnt = 0;
    __syncthreads();

    // Phase 1: coalesced scan of this half of x.
    const int base = sub * HALF;
#pragma unroll
    for (int jj = 0; jj < HALF / 512; jj++) {
        const int t = base + jj * 512 + tid;
        const int v = __ldg(&x[t]);
        if (v / 786 == bin) {
            const int pos = atomicAdd(&s_cnt, 1);
            s_list[pos] = make_int2(t, v);
        }
    }
    __syncthreads();
    const int n = s_cnt;

    // Phase 2: process list entries, group g takes j = g, g+4, g+8, ...
    // Depth-2 rolling prefetch on the list->L chain.
    int  jc = g;
    int2 tc = (jc < n) ? s_list[jc] : make_int2(0, 0);
    float lc = __ldg(&L[(size_t)tc.y * 16 + i]);

    while (jc < n) {
        const int jn = jc + 4;
        const int2 tn = (jn < n) ? s_list[jn] : tc;
        const float ln = __ldg(&L[(size_t)tn.y * 16 + i]);

        float* op = out + (size_t)tc.x * 1024 + (kr << 5) + osub;
        asm volatile("st.global.v8.f32 [%0], {%1,%2,%3,%4,%5,%6,%7,%8};"
            :: "l"(op),
               "f"(lc * r0), "f"(lc * r1), "f"(lc * r2), "f"(lc * r3),
               "f"(lc * r4), "f"(lc * r5), "f"(lc * r6), "f"(lc * r7)
            : "memory");

        jc = jn; tc = tn; lc = ln;
    }
}

extern "C" void kernel_launch(void* const* d_in, const int* in_sizes, int n_in,
                              void* d_out, int out_size) {
    const int*   x = (const int*)  d_in[0];   // (8, 2048) int32
    const float* L = (const float*)d_in[1];   // (64, 786, 16) f32
    const float* R = (const float*)d_in[2];   // (32, 32, 32) f32
    // d_in[3] = p : analytically folded (perfect_shuffle(64, 1024))

    monarch_bin_kernel<<<NBIN * 2, 512>>>(x, L, R, (float*)d_out);
}

// round 13
// speedup vs baseline: 1.0019x; 1.0019x over previous
#include <cuda_runtime.h>
#include <cstdint>
#include <cstddef>

// Monarch embedding, analytically folded:
//   out[tok][kr*32+o] = (kr&1 == s) ? L[v*16 + kr/2] * R[(kr*32 + c)*32 + o] : 0
//   v = x[tok], k = v/786, s = k>>5, c = k&31.
//
// R13 = R12's register-resident-R binning at R5-class occupancy.
// Grid 1024 (64 bins x 16 subs) x 256 thr (~7 CTAs/SM). Each CTA:
//   phase 1: scan its 1024-token slice of x (4 coalesced loads/thread,
//            x is L2-hot), push k==bin matches into an smem list (~16).
//   phase 2: c,s are CTA constants -> each thread's 8-float R slice with
//            parity zeros pre-folded lives in registers. Per token: uniform
//            LDS + L-scalar LDG (depth-2 prefetch) + 8 FMUL + STG.256.
//            ZERO R memory traffic in the hot loop.
// Output row offset for thread = slot*8 (slot = tid&127): fully coalesced.
// List order from atomics is replay-nondeterministic; each token writes only
// its own row -> output invariant.

#define NBIN 64
#define SUBS 16
#define SCAN 1024                // tokens scanned per CTA
#define LCAP 128                 // mean 16, sd 4 -> 28 sigma margin

__global__ void __launch_bounds__(256) monarch_bin_kernel(
    const int* __restrict__ x,
    const float* __restrict__ L,
    const float* __restrict__ R,
    float* __restrict__ out)
{
    __shared__ int  s_cnt;
    __shared__ int2 s_list[LCAP];

    const int bin = blockIdx.x >> 4;        // 0..63
    const int sub = blockIdx.x & (SUBS - 1);
    const int s   = bin >> 5;
    const int c   = bin & 31;

    const int tid  = threadIdx.x;
    const int g    = tid >> 7;              // token-group 0/1
    const int slot = tid & 127;
    const int kr   = slot >> 2;             // 0..31
    const int osub = (slot & 3) << 3;       // 0,8,16,24
    const int i    = slot >> 3;             // L column = kr>>1
    const int p    = kr & 1;                // row parity

    // Register-resident R slice, parity pre-folded to zeros.
    float r0=0.f,r1=0.f,r2=0.f,r3=0.f,r4=0.f,r5=0.f,r6=0.f,r7=0.f;
    if (p == s) {
        const float* rp = &R[((size_t)((kr << 5) + c) << 5) + osub];
        const float4 a = *reinterpret_cast<const float4*>(rp);
        const float4 b = *reinterpret_cast<const float4*>(rp + 4);
        r0=a.x; r1=a.y; r2=a.z; r3=a.w; r4=b.x; r5=b.y; r6=b.z; r7=b.w;
    }

    if (tid == 0) s_cnt = 0;
    __syncthreads();

    // Phase 1: scan this CTA's 1024-token slice (coalesced, L2-hot).
    const int base = sub * SCAN;
#pragma unroll
    for (int jj = 0; jj < SCAN / 256; jj++) {
        const int t = base + jj * 256 + tid;
        const int v = __ldg(&x[t]);
        if (v / 786 == bin) {
            const int pos = atomicAdd(&s_cnt, 1);
            s_list[pos] = make_int2(t, v);
        }
    }
    __syncthreads();
    const int n = s_cnt;

    // Phase 2: token-group g takes entries j = g, g+2, ... Depth-2 prefetch.
    int  jc = g;
    int2 tc = (jc < n) ? s_list[jc] : make_int2(0, 0);
    float lc = __ldg(&L[(size_t)tc.y * 16 + i]);

    while (jc < n) {
        const int  jn = jc + 2;
        const int2 tn = (jn < n) ? s_list[jn] : tc;
        const float ln = __ldg(&L[(size_t)tn.y * 16 + i]);

        float* op = out + (size_t)tc.x * 1024 + (slot << 3);
        asm volatile("st.global.v8.f32 [%0], {%1,%2,%3,%4,%5,%6,%7,%8};"
            :: "l"(op),
               "f"(lc * r0), "f"(lc * r1), "f"(lc * r2), "f"(lc * r3),
               "f"(lc * r4), "f"(lc * r5), "f"(lc * r6), "f"(lc * r7)
            : "memory");

        jc = jn; tc = tn; lc = ln;
    }
}

extern "C" void kernel_launch(void* const* d_in, const int* in_sizes, int n_in,
                              void* d_out, int out_size) {
    const int*   x = (const int*)  d_in[0];   // (8, 2048) int32
    const float* L = (const float*)d_in[1];   // (64, 786, 16) f32
    const float* R = (const float*)d_in[2];   // (32, 32, 32) f32
    // d_in[3] = p : analytically folded (perfect_shuffle(64, 1024))

    monarch_bin_kernel<<<NBIN * SUBS, 256>>>(x, L, R, (float*)d_out);
}

// round 15
// speedup vs baseline: 1.1579x; 1.1557x over previous
#include <cuda_runtime.h>
#include <cstdint>
#include <cstddef>

// Monarch embedding, analytically folded:
//   out[tok][kr*32+o] = (kr&1 == s) ? L[v*16 + kr/2] * R[(kr*32 + c)*32 + o] : 0
//   v = x[tok], k = v/786, s = k>>5, c = k&31.
//
// R14 = R11 (best: parity-pure v8 warps, zero-warps store-only) + cache
// micro-tuning:
//   - st.global.cs on output (streaming 64MiB, never re-read -> evict-first)
//   - ld.global.nc.L1::evict_last on R (pin 128KB R in 228KB L1)
//   - both R loads before both stores: two independent store chains drain
//     back-to-back.
// Map: 256 thr, th = tid>>7 (token of pair), slot = tid&127,
//   u = slot>>5, l = slot&31, p = u&1 (warp parity, uniform),
//   kr = ((u>>1)<<4) + ((l>>2)<<1) + p, osub = (l&3)*8, i = kr>>1.
// Coverage per token-half: 4 warps x 8 rows x 32B = full 4KB row.

__global__ void __launch_bounds__(256) monarch_embed_kernel(
    const int* __restrict__ x,
    const float* __restrict__ L,
    const float* __restrict__ R,
    float* __restrict__ out)
{
    const int tb   = blockIdx.x << 2;      // 4 tokens per CTA
    const int tid  = threadIdx.x;
    const int th   = tid >> 7;             // 0/1: token of each pair
    const int slot = tid & 127;
    const int u    = slot >> 5;            // warp within token-half
    const int l    = slot & 31;
    const int p    = u & 1;                // warp parity (uniform)
    const int kr   = ((u >> 1) << 4) + ((l >> 2) << 1) + p;   // 0..31
    const int osub = (l & 3) << 3;         // 0,8,16,24
    const int i    = kr >> 1;              // L column 0..15

    // One aligned 128-bit load covers x for all 4 tokens.
    const int4 xv = *reinterpret_cast<const int4*>(x + tb);
    const int v0 = th ? xv.y : xv.x;       // pass-0 token
    const int v1 = th ? xv.w : xv.z;       // pass-1 token

    const int k0 = v0 / 786, s0 = k0 >> 5, c0 = k0 & 31;
    const int k1 = v1 / 786, s1 = k1 >> 5, c1 = k1 & 31;
    const bool a0 = (s0 == p), a1 = (s1 == p);   // warp-uniform

    // Long-latency L gathers early, active tokens only.
    float lva = 0.0f, lvb = 0.0f;
    if (a0) lva = __ldg(&L[(size_t)v0 * 16 + i]);
    if (a1) lvb = __ldg(&L[(size_t)v1 * 16 + i]);

    // R v8 loads (L1-pinned via evict_last), active tokens only.
    float q0=0.f,q1=0.f,q2=0.f,q3=0.f,q4=0.f,q5=0.f,q6=0.f,q7=0.f;
    float w0=0.f,w1=0.f,w2=0.f,w3=0.f,w4=0.f,w5=0.f,w6=0.f,w7=0.f;
    if (a0) {
        const float* rp = &R[((size_t)((kr << 5) + c0) << 5) + osub];
        asm("ld.global.nc.L1::evict_last.v8.f32 "
            "{%0,%1,%2,%3,%4,%5,%6,%7}, [%8];"
            : "=f"(q0), "=f"(q1), "=f"(q2), "=f"(q3),
              "=f"(q4), "=f"(q5), "=f"(q6), "=f"(q7)
            : "l"(rp));
        q0*=lva; q1*=lva; q2*=lva; q3*=lva; q4*=lva; q5*=lva; q6*=lva; q7*=lva;
    }
    if (a1) {
        const float* rp = &R[((size_t)((kr << 5) + c1) << 5) + osub];
        asm("ld.global.nc.L1::evict_last.v8.f32 "
            "{%0,%1,%2,%3,%4,%5,%6,%7}, [%8];"
            : "=f"(w0), "=f"(w1), "=f"(w2), "=f"(w3),
              "=f"(w4), "=f"(w5), "=f"(w6), "=f"(w7)
            : "l"(rp));
        w0*=lvb; w1*=lvb; w2*=lvb; w3*=lvb; w4*=lvb; w5*=lvb; w6*=lvb; w7*=lvb;
    }

    // Two streaming stores back-to-back (independent chains).
    float* ob = out + (size_t)(tb + th) * 1024 + (kr << 5) + osub;
    asm volatile("st.global.cs.v8.f32 [%0], {%1,%2,%3,%4,%5,%6,%7,%8};"
        :: "l"(ob),
           "f"(q0), "f"(q1), "f"(q2), "f"(q3),
           "f"(q4), "f"(q5), "f"(q6), "f"(q7) : "memory");
    asm volatile("st.global.cs.v8.f32 [%0], {%1,%2,%3,%4,%5,%6,%7,%8};"
        :: "l"(ob + 2048),
           "f"(w0), "f"(w1), "f"(w2), "f"(w3),
           "f"(w4), "f"(w5), "f"(w6), "f"(w7) : "memory");
}

extern "C" void kernel_launch(void* const* d_in, const int* in_sizes, int n_in,
                              void* d_out, int out_size) {
    const int*   x = (const int*)  d_in[0];   // (8, 2048) int32
    const float* L = (const float*)d_in[1];   // (64, 786, 16) f32
    const float* R = (const float*)d_in[2];   // (32, 32, 32) f32
    // d_in[3] = p : analytically folded (perfect_shuffle(64, 1024))

    const int ntok = out_size / 1024;         // 16384 tokens
    monarch_embed_kernel<<<ntok / 4, 256>>>(x, L, R, (float*)d_out);
}